// round 4
// baseline (speedup 1.0000x reference)
#include <cuda_runtime.h>
#include <math.h>

#define NCLS 1000
#define BATCH 1024
#define BETA 0.7f
#define LAMBDA1 3.0f
#define CLIP_EPS 1e-4f
#define THREADS 256
#define PER_THREAD 4        // 256*4 = 1024 >= 1000

#define ROW_BLOCKS  BATCH   // 1024 blocks do loss rows
#define COPY_BLOCKS 1184    // 148 SMs * 8 do the bulk copy
#define TOT_BLOCKS  (ROW_BLOCKS + COPY_BLOCKS)

// per-row loss partials (ce + LAMBDA1*elr), unique slot per row -> no atomics
__device__ float        g_part[BATCH];
__device__ unsigned int g_count;   // zero at module load; last block resets to 0

// block-wide reduction (sum if SUM=true else max), result broadcast
template <bool SUM>
__device__ __forceinline__ float block_reduce(float val, float* sred) {
    #pragma unroll
    for (int o = 16; o > 0; o >>= 1) {
        float other = __shfl_xor_sync(0xFFFFFFFFu, val, o);
        val = SUM ? (val + other) : fmaxf(val, other);
    }
    int lane = threadIdx.x & 31;
    int warp = threadIdx.x >> 5;
    if (lane == 0) sred[warp] = val;
    __syncthreads();
    if (warp == 0) {
        val = (lane < (THREADS / 32)) ? sred[lane] : (SUM ? 0.0f : -INFINITY);
        #pragma unroll
        for (int o = 4; o > 0; o >>= 1) {
            float other = __shfl_xor_sync(0xFFFFFFFFu, val, o);
            val = SUM ? (val + other) : fmaxf(val, other);
        }
        if (lane == 0) sred[0] = val;
    }
    __syncthreads();
    float r = sred[0];
    __syncthreads();
    return r;
}

__global__ __launch_bounds__(THREADS) void elr_fused_kernel(
    const float* __restrict__ logits,   // [BATCH, NCLS]
    const float* __restrict__ target,   // [200000, NCLS]
    const int*   __restrict__ label,    // [BATCH]
    const int*   __restrict__ index_p,  // [1]
    float*       __restrict__ out,      // out[0]=loss, out+1 = new_target
    long long n,                        // target element count
    int write_target)
{
    __shared__ float sred[32];
    __shared__ bool  s_last;

    const int tid = threadIdx.x;
    const long long lo = (long long)index_p[0] * BATCH * NCLS;  // updated range
    const long long hi = lo + (long long)BATCH * NCLS;
    float* __restrict__ dst = out + 1;

    if (blockIdx.x < ROW_BLOCKS) {
        // ----------------- loss row work -----------------
        const int row = blockIdx.x;
        const float* x = logits + (size_t)row * NCLS;

        float v[PER_THREAD];
        #pragma unroll
        for (int k = 0; k < PER_THREAD; k++) {
            int i = tid + k * THREADS;
            v[k] = (i < NCLS) ? x[i] : -INFINITY;
        }

        // 1) max
        float m = v[0];
        #pragma unroll
        for (int k = 1; k < PER_THREAD; k++) m = fmaxf(m, v[k]);
        m = block_reduce<false>(m, sred);

        // 2) sum of exp
        float e[PER_THREAD];
        float lsum = 0.0f;
        #pragma unroll
        for (int k = 0; k < PER_THREAD; k++) {
            int i = tid + k * THREADS;
            e[k] = (i < NCLS) ? expf(v[k] - m) : 0.0f;
            lsum += e[k];
        }
        const float sumexp = block_reduce<true>(lsum, sred);
        const float inv_sumexp = 1.0f / sumexp;

        // 3) y_pred = clip(softmax) and its sum
        float yp[PER_THREAD];
        float lclip = 0.0f;
        #pragma unroll
        for (int k = 0; k < PER_THREAD; k++) {
            int i = tid + k * THREADS;
            if (i < NCLS) {
                float p = e[k] * inv_sumexp;
                p = fminf(fmaxf(p, CLIP_EPS), 1.0f - CLIP_EPS);
                yp[k] = p;
                lclip += p;
            } else {
                yp[k] = 0.0f;
            }
        }
        const float sclip = block_reduce<true>(lclip, sred);
        const float inv_sclip = 1.0f / sclip;

        // 4) EMA row update + dot(new_row, y_pred)
        const float* trow = target + lo + (size_t)row * NCLS;
        float* drow = dst + lo + (size_t)row * NCLS;

        float ldot = 0.0f;
        #pragma unroll
        for (int k = 0; k < PER_THREAD; k++) {
            int i = tid + k * THREADS;
            if (i < NCLS) {
                float yn = yp[k] * inv_sclip;
                float nr = BETA * trow[i] + (1.0f - BETA) * yn;
                if (write_target) drow[i] = nr;
                ldot += nr * yp[k];
            }
        }
        const float dot = block_reduce<true>(ldot, sred);

        // 5) per-row partial: ce + LAMBDA1 * elr
        if (tid == 0) {
            const int lab = label[row];
            const float ce  = -(x[lab] - m - logf(sumexp));
            const float elr = logf(1.0f - dot);
            g_part[row] = ce + LAMBDA1 * elr;
        }
    } else if (write_target) {
        // ----------------- shifted bulk copy (skips [lo,hi)) -----------------
        const int cid = blockIdx.x - ROW_BLOCKS;
        const long long gid    = (long long)cid * THREADS + tid;
        const long long stride = (long long)COPY_BLOCKS * THREADS;

        // head: elements 0..2 (so dst+3 is 16B-aligned)
        if (gid < 3) {
            long long i = gid;
            if (i < lo || i >= hi) dst[i] = __ldcs(target + i);
        }

        const long long nvec = (n - 3) >> 2;
        for (long long vIdx = gid; vIdx < nvec; vIdx += stride) {
            const long long e0 = 3 + (vIdx << 2);   // first element of this vec
            if (e0 >= lo && e0 + 3 < hi) continue;  // fully inside updated rows
            const float* s = target + e0;
            if (e0 + 3 < lo || e0 >= hi) {
                float4 val;
                val.x = __ldcs(s + 0);
                val.y = __ldcs(s + 1);
                val.z = __ldcs(s + 2);
                val.w = __ldcs(s + 3);
                __stcs((float4*)(dst + e0), val);
            } else {
                // straddles the boundary: scalar with predicate
                #pragma unroll
                for (int j = 0; j < 4; j++) {
                    long long i = e0 + j;
                    if (i < lo || i >= hi) dst[i] = __ldcs(target + i);
                }
            }
        }

        // tail
        const long long tail_start = 3 + (((n - 3) >> 2) << 2);
        for (long long i = tail_start + gid; i < n; i += stride) {
            if (i < lo || i >= hi) dst[i] = __ldcs(target + i);
        }
    }

    // ----------------- completion: last block reduces partials -----------------
    __threadfence();
    __syncthreads();
    if (tid == 0) {
        unsigned int t = atomicAdd(&g_count, 1u);
        s_last = (t == TOT_BLOCKS - 1);
    }
    __syncthreads();

    if (s_last) {
        __threadfence();
        float lsum = 0.0f;
        #pragma unroll
        for (int k = 0; k < BATCH / THREADS; k++) {
            lsum += g_part[tid + k * THREADS];
        }
        const float total = block_reduce<true>(lsum, sred);
        if (tid == 0) {
            out[0] = total * (1.0f / BATCH);
            g_count = 0;   // restore invariant for next launch / graph replay
        }
    }
}

extern "C" void kernel_launch(void* const* d_in, const int* in_sizes, int n_in,
                              void* d_out, int out_size) {
    const float* logits = (const float*)d_in[0];
    const float* target = (const float*)d_in[1];
    const int*   label  = (const int*)d_in[2];
    const int*   index  = (const int*)d_in[3];
    float* out = (float*)d_out;

    const long long tgt_elems = (long long)in_sizes[1];   // 200,000,000
    const int write_target = (out_size > 1) ? 1 : 0;

    elr_fused_kernel<<<TOT_BLOCKS, THREADS>>>(logits, target, label, index,
                                              out, tgt_elems, write_target);
}